// round 15
// baseline (speedup 1.0000x reference)
#include <cuda_runtime.h>
#include <cuda_fp16.h>
#include <cstdint>

#define NV  400000
#define ND  16
#define TPB 256          // pack kernel block size
#define RTPB 64          // rigid kernel block size (12 CTAs/SM, same 24 warps)
#define VPACK 512        // vertices per pack block (2 per thread)

// Packed per-vertex coords: {src.x,src.y,src.z,trg.x,trg.y,trg.z} as 6 fp16 + pad = 16B.
__device__ uint4 g_packed[NV];
__device__ float g_num, g_den;

__device__ __forceinline__ unsigned int h2bits(__half2 h) {
    return *reinterpret_cast<unsigned int*>(&h);
}

__device__ __forceinline__ void unpack6(uint4 p, float& a, float& b, float& c,
                                        float& d, float& e, float& f) {
    float2 f0 = __half22float2(*reinterpret_cast<__half2*>(&p.x));
    float2 f1 = __half22float2(*reinterpret_cast<__half2*>(&p.y));
    float2 f2 = __half22float2(*reinterpret_cast<__half2*>(&p.z));
    a = f0.x; b = f0.y; c = f1.x; d = f1.y; e = f2.x; f = f2.y;
}

__device__ __forceinline__ uint4 make_packed(float sx, float sy, float sz,
                                             float tx, float ty, float tz) {
    uint4 p;
    p.x = h2bits(__floats2half2_rn(sx, sy));
    p.y = h2bits(__floats2half2_rn(sz, tx));
    p.z = h2bits(__floats2half2_rn(ty, tz));
    p.w = 0u;
    return p;
}

// Smem-cooperative pack (R12, proven): 512 vertices per block; 256 threads
// stream 384 float4 per array into smem, each thread packs two vertices.
__global__ void pack_kernel(const float* __restrict__ trg,
                            const float* __restrict__ src, int V) {
    __shared__ float ss[3 * VPACK];
    __shared__ float st[3 * VPACK];
    const int tid = threadIdx.x;
    const int vbase = blockIdx.x * VPACK;
    if (tid == 0 && blockIdx.x == 0) { g_num = 0.f; g_den = 0.f; }
    if (vbase >= V) return;

    int nverts = min(VPACK, V - vbase);
    int nf4 = (nverts * 3 + 3) >> 2;
    const float4* s4 = reinterpret_cast<const float4*>(src) + (size_t)vbase * 3 / 4;
    const float4* t4 = reinterpret_cast<const float4*>(trg) + (size_t)vbase * 3 / 4;
    #pragma unroll
    for (int k = 0; k < 2; k++) {
        int i = tid + k * TPB;
        if (i < nf4) {
            reinterpret_cast<float4*>(ss)[i] = s4[i];
            reinterpret_cast<float4*>(st)[i] = t4[i];
        }
    }
    __syncthreads();

    #pragma unroll
    for (int k = 0; k < 2; k++) {
        int l = tid + k * TPB;
        int v = vbase + l;
        if (l < nverts && v < V) {
            g_packed[v] = make_packed(ss[3*l+0], ss[3*l+1], ss[3*l+2],
                                      st[3*l+0], st[3*l+1], st[3*l+2]);
        }
    }
}

// R14 rigid body at quarter granularity: 64 threads x 12 CTAs/SM = same 24
// warps/SM (register-file cap: 64*80*12 = 61.4k <= 64k), 6252 blocks.
// CTA-granularity halving won 3us in R14 (finer dynamic backfill + halved
// drain tail); this pushes the same lever one more step. Body bit-identical.
__global__ void __launch_bounds__(RTPB, 12)
rigid_kernel(const int* __restrict__ nbr,
             const float* __restrict__ wts, int V) {
    // [d][component-pair][tid] fp16 cache of (s,t) vectors: 16*3*64 half2 = 12KB.
    __shared__ __half2 sh[ND * 3 * RTPB];
    const int tid = threadIdx.x;
    const int v = blockIdx.x * RTPB + tid;

    float num = 0.f, den = 0.f;

    if (v < V) {
        // Center coords (coalesced 16B load from packed array).
        float csx, csy, csz, ctx, cty, ctz;
        {
            uint4 pc = g_packed[v];
            unpack6(pc, csx, csy, csz, ctx, cty, ctz);
        }

        // 16 int32 indices = 64B contiguous; 4x LDG.128.
        int idx[ND];
        const int4* ip = reinterpret_cast<const int4*>(nbr + (long long)v * ND);
        #pragma unroll
        for (int k = 0; k < ND / 4; k++) {
            int4 q = ip[k];
            idx[4*k+0] = q.x;
            idx[4*k+1] = q.y;
            idx[4*k+2] = q.z;
            idx[4*k+3] = q.w;
        }

        // Pass 1: gather neighbors, build cross-covariance M, cache (s,t) in SMEM.
        float m00=0,m01=0,m02=0,m10=0,m11=0,m12=0,m20=0,m21=0,m22=0;
        #pragma unroll
        for (int d = 0; d < ND; d++) {
            uint4 p = g_packed[idx[d]];           // single LDG.128 per neighbor
            float a,b,c,e,f,g;
            unpack6(p, a, b, c, e, f, g);
            float s0 = a - csx, s1 = b - csy, s2 = c - csz;
            float t0 = e - ctx, t1 = f - cty, t2 = g - ctz;
            m00 = fmaf(s0,t0,m00); m01 = fmaf(s0,t1,m01); m02 = fmaf(s0,t2,m02);
            m10 = fmaf(s1,t0,m10); m11 = fmaf(s1,t1,m11); m12 = fmaf(s1,t2,m12);
            m20 = fmaf(s2,t0,m20); m21 = fmaf(s2,t1,m21); m22 = fmaf(s2,t2,m22);
            sh[(d*3+0)*RTPB + tid] = __floats2half2_rn(s0, s1);
            sh[(d*3+1)*RTPB + tid] = __floats2half2_rn(s2, t0);
            sh[(d*3+2)*RTPB + tid] = __floats2half2_rn(t1, t2);
        }
        m00 += 1e-6f; m11 += 1e-6f; m22 += 1e-6f;

        // Polar factor of M via det-scaled Newton: X <- 0.5*(mu*X + (1/mu)*X^-T).
        // Converges to U@Vh of the SVD (sign-preserving), matching the reference.
        float x00=m00,x01=m01,x02=m02,x10=m10,x11=m11,x12=m12,x20=m20,x21=m21,x22=m22;
        #pragma unroll
        for (int it = 0; it < 6; it++) {
            float c00 = fmaf(x11,x22,-x12*x21);
            float c01 = fmaf(x12,x20,-x10*x22);
            float c02 = fmaf(x10,x21,-x11*x20);
            float c10 = fmaf(x02,x21,-x01*x22);
            float c11 = fmaf(x00,x22,-x02*x20);
            float c12 = fmaf(x01,x20,-x00*x21);
            float c20 = fmaf(x01,x12,-x02*x11);
            float c21 = fmaf(x02,x10,-x00*x12);
            float c22 = fmaf(x00,x11,-x01*x10);
            float det = fmaf(x00,c00, fmaf(x01,c01, x02*c02));
            float ad  = fmaxf(fabsf(det), 1e-30f);
            float mu  = __powf(ad, -0.33333334f);     // MUFU lg2 + ex2
            float aa  = 0.5f * mu;
            float bb  = 0.5f / (mu * det);            // 0.5 * mu^-1 * det^-1
            x00 = fmaf(aa,x00, bb*c00); x01 = fmaf(aa,x01, bb*c01); x02 = fmaf(aa,x02, bb*c02);
            x10 = fmaf(aa,x10, bb*c10); x11 = fmaf(aa,x11, bb*c11); x12 = fmaf(aa,x12, bb*c12);
            x20 = fmaf(aa,x20, bb*c20); x21 = fmaf(aa,x21, bb*c21); x22 = fmaf(aa,x22, bb*c22);
        }

        // Pass 2: residuals from SMEM cache (no re-gather), weighted accumulation.
        const float4* wp = reinterpret_cast<const float4*>(wts + (long long)v * ND);
        #pragma unroll
        for (int k = 0; k < ND / 4; k++) {
            float4 w4 = wp[k];
            float wv[4] = {w4.x, w4.y, w4.z, w4.w};
            #pragma unroll
            for (int j = 0; j < 4; j++) {
                int d = k*4 + j;
                float2 f0 = __half22float2(sh[(d*3+0)*RTPB + tid]);
                float2 f1 = __half22float2(sh[(d*3+1)*RTPB + tid]);
                float2 f2 = __half22float2(sh[(d*3+2)*RTPB + tid]);
                float s0=f0.x, s1=f0.y, s2=f1.x, t0=f1.y, t1=f2.x, t2=f2.y;
                float y0 = fmaf(x00,s0, fmaf(x01,s1, x02*s2)) - t0;
                float y1 = fmaf(x10,s0, fmaf(x11,s1, x12*s2)) - t1;
                float y2 = fmaf(x20,s0, fmaf(x21,s1, x22*s2)) - t2;
                float dd = __fsqrt_rn(fmaf(y0,y0, fmaf(y1,y1, y2*y2)));
                num = fmaf(dd, wv[j], num);
                den += wv[j];
            }
        }
    }

    // Block reduction (2 warps).
    #pragma unroll
    for (int o = 16; o > 0; o >>= 1) {
        num += __shfl_down_sync(0xffffffffu, num, o);
        den += __shfl_down_sync(0xffffffffu, den, o);
    }
    __syncthreads();
    float* red = reinterpret_cast<float*>(sh);
    int warp = tid >> 5;
    if ((tid & 31) == 0) { red[warp] = num; red[2 + warp] = den; }
    __syncthreads();
    if (tid == 0) {
        atomicAdd(&g_num, red[0] + red[1]);
        atomicAdd(&g_den, red[2] + red[3]);
    }
}

__global__ void finalize_kernel(float* __restrict__ out) {
    out[0] = g_num / (g_den + 1e-6f);
}

extern "C" void kernel_launch(void* const* d_in, const int* in_sizes, int n_in,
                              void* d_out, int out_size) {
    const float* trg = (const float*)d_in[0];      // new_verts_coords
    const float* src = (const float*)d_in[1];      // verts_src
    const int*   nbr = (const int*)d_in[2];        // neighborhood_indices (int32)
    const float* wts = (const float*)d_in[3];      // neighborhood_weights
    float* out = (float*)d_out;

    int V = in_sizes[0] / 3;
    int rgrid = (V + RTPB - 1) / RTPB;
    int pack_grid = (V + VPACK - 1) / VPACK;

    pack_kernel<<<pack_grid, TPB>>>(trg, src, V);
    rigid_kernel<<<rgrid, RTPB>>>(nbr, wts, V);
    finalize_kernel<<<1, 1>>>(out);
}

// round 16
// speedup vs baseline: 1.0370x; 1.0370x over previous
#include <cuda_runtime.h>
#include <cuda_fp16.h>
#include <cstdint>

#define NV  400000
#define ND  16
#define TPB 256          // pack kernel block size
#define RTPB 96          // rigid kernel block size (8 CTAs/SM, same 24 warps)
#define VPACK 512        // vertices per pack block (2 per thread)

// Packed per-vertex coords: {src.x,src.y,src.z,trg.x,trg.y,trg.z} as 6 fp16 + pad = 16B.
__device__ uint4 g_packed[NV];
__device__ float g_num, g_den;

__device__ __forceinline__ unsigned int h2bits(__half2 h) {
    return *reinterpret_cast<unsigned int*>(&h);
}

__device__ __forceinline__ void unpack6(uint4 p, float& a, float& b, float& c,
                                        float& d, float& e, float& f) {
    float2 f0 = __half22float2(*reinterpret_cast<__half2*>(&p.x));
    float2 f1 = __half22float2(*reinterpret_cast<__half2*>(&p.y));
    float2 f2 = __half22float2(*reinterpret_cast<__half2*>(&p.z));
    a = f0.x; b = f0.y; c = f1.x; d = f1.y; e = f2.x; f = f2.y;
}

__device__ __forceinline__ uint4 make_packed(float sx, float sy, float sz,
                                             float tx, float ty, float tz) {
    uint4 p;
    p.x = h2bits(__floats2half2_rn(sx, sy));
    p.y = h2bits(__floats2half2_rn(sz, tx));
    p.z = h2bits(__floats2half2_rn(ty, tz));
    p.w = 0u;
    return p;
}

// Smem-cooperative pack (R12, proven): 512 vertices per block; 256 threads
// stream 384 float4 per array into smem, each thread packs two vertices.
__global__ void pack_kernel(const float* __restrict__ trg,
                            const float* __restrict__ src, int V) {
    __shared__ float ss[3 * VPACK];
    __shared__ float st[3 * VPACK];
    const int tid = threadIdx.x;
    const int vbase = blockIdx.x * VPACK;
    if (tid == 0 && blockIdx.x == 0) { g_num = 0.f; g_den = 0.f; }
    if (vbase >= V) return;

    int nverts = min(VPACK, V - vbase);
    int nf4 = (nverts * 3 + 3) >> 2;
    const float4* s4 = reinterpret_cast<const float4*>(src) + (size_t)vbase * 3 / 4;
    const float4* t4 = reinterpret_cast<const float4*>(trg) + (size_t)vbase * 3 / 4;
    #pragma unroll
    for (int k = 0; k < 2; k++) {
        int i = tid + k * TPB;
        if (i < nf4) {
            reinterpret_cast<float4*>(ss)[i] = s4[i];
            reinterpret_cast<float4*>(st)[i] = t4[i];
        }
    }
    __syncthreads();

    #pragma unroll
    for (int k = 0; k < 2; k++) {
        int l = tid + k * TPB;
        int v = vbase + l;
        if (l < nverts && v < V) {
            g_packed[v] = make_packed(ss[3*l+0], ss[3*l+1], ss[3*l+2],
                                      st[3*l+0], st[3*l+1], st[3*l+2]);
        }
    }
}

// Granularity sweep final probe: 96 threads x 8 CTAs/SM = 24 warps/SM
// (regs 96*80*8 = 61.4k <= 64k). Measured valley: 256thr->45.5, 128->42.5,
// 64->43.0; this tests the midpoint. Body bit-identical to R14/R15.
__global__ void __launch_bounds__(RTPB, 8)
rigid_kernel(const int* __restrict__ nbr,
             const float* __restrict__ wts, int V) {
    // [d][component-pair][tid] fp16 cache of (s,t) vectors: 16*3*96 half2 = 18KB.
    __shared__ __half2 sh[ND * 3 * RTPB];
    const int tid = threadIdx.x;
    const int v = blockIdx.x * RTPB + tid;

    float num = 0.f, den = 0.f;

    if (v < V) {
        // Center coords (coalesced 16B load from packed array).
        float csx, csy, csz, ctx, cty, ctz;
        {
            uint4 pc = g_packed[v];
            unpack6(pc, csx, csy, csz, ctx, cty, ctz);
        }

        // 16 int32 indices = 64B contiguous; 4x LDG.128.
        int idx[ND];
        const int4* ip = reinterpret_cast<const int4*>(nbr + (long long)v * ND);
        #pragma unroll
        for (int k = 0; k < ND / 4; k++) {
            int4 q = ip[k];
            idx[4*k+0] = q.x;
            idx[4*k+1] = q.y;
            idx[4*k+2] = q.z;
            idx[4*k+3] = q.w;
        }

        // Pass 1: gather neighbors, build cross-covariance M, cache (s,t) in SMEM.
        float m00=0,m01=0,m02=0,m10=0,m11=0,m12=0,m20=0,m21=0,m22=0;
        #pragma unroll
        for (int d = 0; d < ND; d++) {
            uint4 p = g_packed[idx[d]];           // single LDG.128 per neighbor
            float a,b,c,e,f,g;
            unpack6(p, a, b, c, e, f, g);
            float s0 = a - csx, s1 = b - csy, s2 = c - csz;
            float t0 = e - ctx, t1 = f - cty, t2 = g - ctz;
            m00 = fmaf(s0,t0,m00); m01 = fmaf(s0,t1,m01); m02 = fmaf(s0,t2,m02);
            m10 = fmaf(s1,t0,m10); m11 = fmaf(s1,t1,m11); m12 = fmaf(s1,t2,m12);
            m20 = fmaf(s2,t0,m20); m21 = fmaf(s2,t1,m21); m22 = fmaf(s2,t2,m22);
            sh[(d*3+0)*RTPB + tid] = __floats2half2_rn(s0, s1);
            sh[(d*3+1)*RTPB + tid] = __floats2half2_rn(s2, t0);
            sh[(d*3+2)*RTPB + tid] = __floats2half2_rn(t1, t2);
        }
        m00 += 1e-6f; m11 += 1e-6f; m22 += 1e-6f;

        // Polar factor of M via det-scaled Newton: X <- 0.5*(mu*X + (1/mu)*X^-T).
        // Converges to U@Vh of the SVD (sign-preserving), matching the reference.
        float x00=m00,x01=m01,x02=m02,x10=m10,x11=m11,x12=m12,x20=m20,x21=m21,x22=m22;
        #pragma unroll
        for (int it = 0; it < 6; it++) {
            float c00 = fmaf(x11,x22,-x12*x21);
            float c01 = fmaf(x12,x20,-x10*x22);
            float c02 = fmaf(x10,x21,-x11*x20);
            float c10 = fmaf(x02,x21,-x01*x22);
            float c11 = fmaf(x00,x22,-x02*x20);
            float c12 = fmaf(x01,x20,-x00*x21);
            float c20 = fmaf(x01,x12,-x02*x11);
            float c21 = fmaf(x02,x10,-x00*x12);
            float c22 = fmaf(x00,x11,-x01*x10);
            float det = fmaf(x00,c00, fmaf(x01,c01, x02*c02));
            float ad  = fmaxf(fabsf(det), 1e-30f);
            float mu  = __powf(ad, -0.33333334f);     // MUFU lg2 + ex2
            float aa  = 0.5f * mu;
            float bb  = 0.5f / (mu * det);            // 0.5 * mu^-1 * det^-1
            x00 = fmaf(aa,x00, bb*c00); x01 = fmaf(aa,x01, bb*c01); x02 = fmaf(aa,x02, bb*c02);
            x10 = fmaf(aa,x10, bb*c10); x11 = fmaf(aa,x11, bb*c11); x12 = fmaf(aa,x12, bb*c12);
            x20 = fmaf(aa,x20, bb*c20); x21 = fmaf(aa,x21, bb*c21); x22 = fmaf(aa,x22, bb*c22);
        }

        // Pass 2: residuals from SMEM cache (no re-gather), weighted accumulation.
        const float4* wp = reinterpret_cast<const float4*>(wts + (long long)v * ND);
        #pragma unroll
        for (int k = 0; k < ND / 4; k++) {
            float4 w4 = wp[k];
            float wv[4] = {w4.x, w4.y, w4.z, w4.w};
            #pragma unroll
            for (int j = 0; j < 4; j++) {
                int d = k*4 + j;
                float2 f0 = __half22float2(sh[(d*3+0)*RTPB + tid]);
                float2 f1 = __half22float2(sh[(d*3+1)*RTPB + tid]);
                float2 f2 = __half22float2(sh[(d*3+2)*RTPB + tid]);
                float s0=f0.x, s1=f0.y, s2=f1.x, t0=f1.y, t1=f2.x, t2=f2.y;
                float y0 = fmaf(x00,s0, fmaf(x01,s1, x02*s2)) - t0;
                float y1 = fmaf(x10,s0, fmaf(x11,s1, x12*s2)) - t1;
                float y2 = fmaf(x20,s0, fmaf(x21,s1, x22*s2)) - t2;
                float dd = __fsqrt_rn(fmaf(y0,y0, fmaf(y1,y1, y2*y2)));
                num = fmaf(dd, wv[j], num);
                den += wv[j];
            }
        }
    }

    // Block reduction (3 warps).
    #pragma unroll
    for (int o = 16; o > 0; o >>= 1) {
        num += __shfl_down_sync(0xffffffffu, num, o);
        den += __shfl_down_sync(0xffffffffu, den, o);
    }
    __syncthreads();
    float* red = reinterpret_cast<float*>(sh);
    int warp = tid >> 5;
    if ((tid & 31) == 0) { red[warp] = num; red[3 + warp] = den; }
    __syncthreads();
    if (tid == 0) {
        atomicAdd(&g_num, red[0] + red[1] + red[2]);
        atomicAdd(&g_den, red[3] + red[4] + red[5]);
    }
}

__global__ void finalize_kernel(float* __restrict__ out) {
    out[0] = g_num / (g_den + 1e-6f);
}

extern "C" void kernel_launch(void* const* d_in, const int* in_sizes, int n_in,
                              void* d_out, int out_size) {
    const float* trg = (const float*)d_in[0];      // new_verts_coords
    const float* src = (const float*)d_in[1];      // verts_src
    const int*   nbr = (const int*)d_in[2];        // neighborhood_indices (int32)
    const float* wts = (const float*)d_in[3];      // neighborhood_weights
    float* out = (float*)d_out;

    int V = in_sizes[0] / 3;
    int rgrid = (V + RTPB - 1) / RTPB;
    int pack_grid = (V + VPACK - 1) / VPACK;

    pack_kernel<<<pack_grid, TPB>>>(trg, src, V);
    rigid_kernel<<<rgrid, RTPB>>>(nbr, wts, V);
    finalize_kernel<<<1, 1>>>(out);
}